// round 10
// baseline (speedup 1.0000x reference)
#include <cuda_runtime.h>

#define TSEQ 512
#define BB 16
#define NTHREADS 128
#define BATCH 2048
#define NBLOCKS (BATCH / BB)   // 128

// smem layout (float indices)
// weights interleaved over k-pairs: WP[k2][j][p] = w[j*64 + 2*k2 + p], k2=0..31
#define OFF_WP0   0
#define OFF_WPI1  16384
#define OFF_WPH1  32768
#define OFF_GB    49152      // gbuf [16][256]
#define OFF_H0    53248      // h0 [16][64]
#define OFF_H1    54272      // h1 [16][64]
#define OFF_XB    55296      // [16]
#define SMEM_FLOATS (OFF_XB + 16)
#define SMEM_BYTES  (SMEM_FLOATS * 4)   // 221248

typedef unsigned long long ull;

__device__ __forceinline__ void unpack2(ull v, float& lo, float& hi){
    asm("mov.b64 {%0,%1}, %2;" : "=f"(lo), "=f"(hi) : "l"(v));
}
__device__ __forceinline__ ull ffma2(ull a, ull b, ull c){
    ull d; asm("fma.rn.f32x2 %0, %1, %2, %3;" : "=l"(d) : "l"(a), "l"(b), "l"(c)); return d;
}
__device__ __forceinline__ float fast_ex2(float x){ float y; asm("ex2.approx.f32 %0, %1;" : "=f"(y) : "f"(x)); return y; }
__device__ __forceinline__ float fast_rcp(float x){ float y; asm("rcp.approx.f32 %0, %1;" : "=f"(y) : "f"(x)); return y; }

__device__ __forceinline__ float tanh_(float v){
    float e = fast_ex2(-2.8853900817779268f * v);
    return fmaf(2.0f, fast_rcp(1.0f + e), -1.0f);
}

// acc[c][bb] += sum_k h[bb][k] * W[k][j0+c] for all 16 batch rows.
// WP: [k2][256][2] interleaved; hrow: [16 rows][64] fp32 (broadcast loads).
// Weights double-buffered; h front-batched (16 indep LDS.128 ahead of 64 FFMA2).
__device__ __forceinline__ void gemm_k64(ull acc[2][16], const float* __restrict__ WP,
                                         const float* __restrict__ hrow, int j0)
{
    const float* wp = WP + j0 * 2;
    ulonglong2 wa = *(const ulonglong2*)(wp);
    ulonglong2 wb = *(const ulonglong2*)(wp + 512);

    #pragma unroll
    for (int k4 = 0; k4 < 16; ++k4) {
        ulonglong2 hv[16];
        #pragma unroll
        for (int bb = 0; bb < 16; ++bb)
            hv[bb] = *(const ulonglong2*)(hrow + bb * 64 + 4 * k4);

        ulonglong2 wa_n, wb_n;
        if (k4 < 15) {
            wa_n = *(const ulonglong2*)(wp + (k4 + 1) * 1024);
            wb_n = *(const ulonglong2*)(wp + (k4 + 1) * 1024 + 512);
        }

        #pragma unroll
        for (int bb = 0; bb < 16; ++bb) {
            acc[0][bb] = ffma2(hv[bb].x, wa.x, acc[0][bb]);
            acc[1][bb] = ffma2(hv[bb].x, wa.y, acc[1][bb]);
            acc[0][bb] = ffma2(hv[bb].y, wb.x, acc[0][bb]);
            acc[1][bb] = ffma2(hv[bb].y, wb.y, acc[1][bb]);
        }
        wa = wa_n; wb = wb_n;
    }
}

__global__ __launch_bounds__(NTHREADS)
void lstm2_fused_kernel(const float* __restrict__ x,
                        const float* __restrict__ w_ih0, const float* __restrict__ w_hh0,
                        const float* __restrict__ b_ih0, const float* __restrict__ b_hh0,
                        const float* __restrict__ w_ih1, const float* __restrict__ w_hh1,
                        const float* __restrict__ b_ih1, const float* __restrict__ b_hh1,
                        const float* __restrict__ w_fc,  const float* __restrict__ b_fc,
                        float* __restrict__ out)
{
    extern __shared__ float smem[];
    float* WP0  = smem + OFF_WP0;
    float* WPI1 = smem + OFF_WPI1;
    float* WPH1 = smem + OFF_WPH1;
    float* gbuf = smem + OFF_GB;
    float* h0s  = smem + OFF_H0;
    float* h1s  = smem + OFF_H1;
    float* xbuf = smem + OFF_XB;

    const int tid   = threadIdx.x;
    const int bbase = blockIdx.x * BB;

    // weights -> smem, k-pair interleaved: WP[(k2*256 + j)*2 + p] = w[j*64 + 2*k2 + p]
    for (int idx = tid; idx < 32 * 256; idx += NTHREADS) {
        int k2 = idx >> 8, j = idx & 255;
        float2 a0 = *(const float2*)(w_hh0 + j * 64 + 2 * k2);
        float2 a1 = *(const float2*)(w_ih1 + j * 64 + 2 * k2);
        float2 a2 = *(const float2*)(w_hh1 + j * 64 + 2 * k2);
        *(float2*)(WP0  + idx * 2) = a0;
        *(float2*)(WPI1 + idx * 2) = a1;
        *(float2*)(WPH1 + idx * 2) = a2;
    }
    for (int idx = tid; idx < BB * 64; idx += NTHREADS) { h0s[idx] = 0.0f; h1s[idx] = 0.0f; }
    if (tid < BB) xbuf[tid] = x[(bbase + tid) * TSEQ + 0];

    // gemm tiling: 2 gate columns x ALL 16 batch elems per thread (zero weight redundancy)
    const int j0 = tid * 2;            // cols j0, j0+1 (tid covers all 128 col-pairs)
    const int g  = tid >> 5;           // gate type, uniform per warp: 0:i 1:f 2:g 3:o
    const float kexp = (g == 2) ? -2.8853900817779268f : -1.4426950408889634f;
    const float amul = (g == 2) ? 2.0f : 1.0f;
    const float aadd = (g == 2) ? -1.0f : 0.0f;

    float bias0c[2], bias1c[2], wi0c[2];
    #pragma unroll
    for (int c = 0; c < 2; ++c) {
        bias0c[c] = b_ih0[j0 + c] + b_hh0[j0 + c];
        bias1c[c] = b_ih1[j0 + c] + b_hh1[j0 + c];
        wi0c[c]   = w_ih0[j0 + c];
    }

    // state-update mapping: 16 bb x 8 threads x 8 hidden units
    const int bb_u = tid >> 3;         // 0..15
    const int m_u  = (tid & 7) * 8;    // 0..56
    float c0[8], c1[8];
    #pragma unroll
    for (int m = 0; m < 8; ++m) { c0[m] = 0.0f; c1[m] = 0.0f; }

    __syncthreads();

    for (int t = 0; t < TSEQ; ++t) {
        ull acc[2][16];

        // ---- layer 0 gates: h0 . Whh0 ----
        #pragma unroll
        for (int c = 0; c < 2; ++c)
            #pragma unroll
            for (int bb = 0; bb < 16; ++bb) acc[c][bb] = 0ULL;
        gemm_k64(acc, WP0, h0s, j0);

        #pragma unroll
        for (int bb = 0; bb < 16; ++bb) {
            float xv = xbuf[bb];
            float2 gv;
            float lo, hi;
            unpack2(acc[0][bb], lo, hi);
            float v0 = fmaf(xv, wi0c[0], bias0c[0]) + (lo + hi);
            unpack2(acc[1][bb], lo, hi);
            float v1 = fmaf(xv, wi0c[1], bias0c[1]) + (lo + hi);
            gv.x = fmaf(amul, fast_rcp(1.0f + fast_ex2(kexp * v0)), aadd);
            gv.y = fmaf(amul, fast_rcp(1.0f + fast_ex2(kexp * v1)), aadd);
            *(float2*)&gbuf[bb * 256 + j0] = gv;
        }
        __syncthreads();

        // ---- layer 0 state update (8 units of one bb per thread) ----
        {
            const float* gb = &gbuf[bb_u * 256 + m_u];
            float* hw = &h0s[bb_u * 64 + m_u];
            #pragma unroll
            for (int q = 0; q < 2; ++q) {
                float4 iv = *(const float4*)&gb[q * 4];
                float4 fv = *(const float4*)&gb[64 + q * 4];
                float4 gv = *(const float4*)&gb[128 + q * 4];
                float4 ov = *(const float4*)&gb[192 + q * 4];
                float* cc = &c0[q * 4];
                cc[0] = fmaf(fv.x, cc[0], iv.x * gv.x);
                cc[1] = fmaf(fv.y, cc[1], iv.y * gv.y);
                cc[2] = fmaf(fv.z, cc[2], iv.z * gv.z);
                cc[3] = fmaf(fv.w, cc[3], iv.w * gv.w);
                float4 hv;
                hv.x = ov.x * tanh_(cc[0]);
                hv.y = ov.y * tanh_(cc[1]);
                hv.z = ov.z * tanh_(cc[2]);
                hv.w = ov.w * tanh_(cc[3]);
                *(float4*)&hw[q * 4] = hv;
            }
        }
        __syncthreads();

        // ---- layer 1 gates: h0 . Wih1 + h1 . Whh1 ----
        #pragma unroll
        for (int c = 0; c < 2; ++c)
            #pragma unroll
            for (int bb = 0; bb < 16; ++bb) acc[c][bb] = 0ULL;
        gemm_k64(acc, WPI1, h0s, j0);
        gemm_k64(acc, WPH1, h1s, j0);

        #pragma unroll
        for (int bb = 0; bb < 16; ++bb) {
            float2 gv;
            float lo, hi;
            unpack2(acc[0][bb], lo, hi);
            float v0 = bias1c[0] + (lo + hi);
            unpack2(acc[1][bb], lo, hi);
            float v1 = bias1c[1] + (lo + hi);
            gv.x = fmaf(amul, fast_rcp(1.0f + fast_ex2(kexp * v0)), aadd);
            gv.y = fmaf(amul, fast_rcp(1.0f + fast_ex2(kexp * v1)), aadd);
            *(float2*)&gbuf[bb * 256 + j0] = gv;
        }
        __syncthreads();

        // ---- layer 1 state update + x prefetch ----
        {
            const float* gb = &gbuf[bb_u * 256 + m_u];
            float* hw = &h1s[bb_u * 64 + m_u];
            #pragma unroll
            for (int q = 0; q < 2; ++q) {
                float4 iv = *(const float4*)&gb[q * 4];
                float4 fv = *(const float4*)&gb[64 + q * 4];
                float4 gv = *(const float4*)&gb[128 + q * 4];
                float4 ov = *(const float4*)&gb[192 + q * 4];
                float* cc = &c1[q * 4];
                cc[0] = fmaf(fv.x, cc[0], iv.x * gv.x);
                cc[1] = fmaf(fv.y, cc[1], iv.y * gv.y);
                cc[2] = fmaf(fv.z, cc[2], iv.z * gv.z);
                cc[3] = fmaf(fv.w, cc[3], iv.w * gv.w);
                float4 hv;
                hv.x = ov.x * tanh_(cc[0]);
                hv.y = ov.y * tanh_(cc[1]);
                hv.z = ov.z * tanh_(cc[2]);
                hv.w = ov.w * tanh_(cc[3]);
                *(float4*)&hw[q * 4] = hv;
            }
        }
        if (t + 1 < TSEQ && tid < BB) xbuf[tid] = x[(bbase + tid) * TSEQ + (t + 1)];
        __syncthreads();
    }

    // ---- final FC ----
    if (tid < BB * 3) {
        int bb  = tid / 3;
        int cls = tid - bb * 3;
        float s = b_fc[cls];
        #pragma unroll 8
        for (int m = 0; m < 64; ++m)
            s = fmaf(h1s[bb * 64 + m], w_fc[cls * 64 + m], s);
        out[(bbase + bb) * 3 + cls] = s;
    }
}

extern "C" void kernel_launch(void* const* d_in, const int* in_sizes, int n_in,
                              void* d_out, int out_size)
{
    const float* x     = (const float*)d_in[0];
    const float* w_ih0 = (const float*)d_in[1];
    const float* w_hh0 = (const float*)d_in[2];
    const float* b_ih0 = (const float*)d_in[3];
    const float* b_hh0 = (const float*)d_in[4];
    const float* w_ih1 = (const float*)d_in[5];
    const float* w_hh1 = (const float*)d_in[6];
    const float* b_ih1 = (const float*)d_in[7];
    const float* b_hh1 = (const float*)d_in[8];
    const float* w_fc  = (const float*)d_in[9];
    const float* b_fc  = (const float*)d_in[10];
    float* out = (float*)d_out;

    cudaFuncSetAttribute(lstm2_fused_kernel,
                         cudaFuncAttributeMaxDynamicSharedMemorySize, SMEM_BYTES);

    lstm2_fused_kernel<<<NBLOCKS, NTHREADS, SMEM_BYTES>>>(
        x, w_ih0, w_hh0, b_ih0, b_hh0,
        w_ih1, w_hh1, b_ih1, b_hh1,
        w_fc, b_fc, out);
}

// round 11
// speedup vs baseline: 1.3612x; 1.3612x over previous
#include <cuda_runtime.h>

#define TSEQ 512
#define BB 16
#define NTHREADS 256
#define BATCH 2048
#define NBLOCKS (BATCH / BB)   // 128

// smem layout (float indices).
// Weight matrices stored gate-adjacent, split into two halves for conflict-free LDS.128:
//   WQa[(k2*64 + m)*4 + g*2 + p] = w[(g*64+m)*64 + 2*k2+p]   for g in {0,1}
//   WQb[(k2*64 + m)*4 + (g-2)*2 + p] = same                  for g in {2,3}
#define OFF_W0A   0
#define OFF_W0B   8192
#define OFF_WI1A  16384
#define OFF_WI1B  24576
#define OFF_WH1A  32768
#define OFF_WH1B  40960
#define OFF_H0    49152      // h0 [16][64]
#define OFF_H1    50176      // h1 [16][64]
#define OFF_XB    51200      // [16]
#define SMEM_FLOATS (OFF_XB + 16)
#define SMEM_BYTES  (SMEM_FLOATS * 4)   // 204864

typedef unsigned long long ull;

__device__ __forceinline__ void unpack2(ull v, float& lo, float& hi){
    asm("mov.b64 {%0,%1}, %2;" : "=f"(lo), "=f"(hi) : "l"(v));
}
__device__ __forceinline__ ull ffma2(ull a, ull b, ull c){
    ull d; asm("fma.rn.f32x2 %0, %1, %2, %3;" : "=l"(d) : "l"(a), "l"(b), "l"(c)); return d;
}
__device__ __forceinline__ float fast_ex2(float x){ float y; asm("ex2.approx.f32 %0, %1;" : "=f"(y) : "f"(x)); return y; }
__device__ __forceinline__ float fast_rcp(float x){ float y; asm("rcp.approx.f32 %0, %1;" : "=f"(y) : "f"(x)); return y; }

__device__ __forceinline__ float sigm_(float v){
    float e = fast_ex2(-1.4426950408889634f * v);
    return fast_rcp(1.0f + e);
}
__device__ __forceinline__ float tanh_(float v){
    float e = fast_ex2(-2.8853900817779268f * v);
    return fmaf(2.0f, fast_rcp(1.0f + e), -1.0f);
}

// acc[g][bb] (ull: k-even/k-odd partial sums) += sum_k h[bb][k] * W[k][g*64+m]
// Wa/Wb: gate-split layout above; hrow: this thread's 4 batch rows [4][64].
__device__ __forceinline__ void gemm_unit(ull acc[4][4],
                                          const float* __restrict__ Wa,
                                          const float* __restrict__ Wb,
                                          const float* __restrict__ hrow, int m4)
{
    const float* wa = Wa + m4;
    const float* wb = Wb + m4;
    #pragma unroll
    for (int k4 = 0; k4 < 16; ++k4) {
        ulonglong2 hv[4];
        #pragma unroll
        for (int bb = 0; bb < 4; ++bb)
            hv[bb] = *(const ulonglong2*)(hrow + bb * 64 + 4 * k4);
        // weights for k2 = 2k4 (A1/B1) and 2k4+1 (A2/B2); 16B lane stride -> conflict-free
        ulonglong2 wA1 = *(const ulonglong2*)(wa + 512 * k4);
        ulonglong2 wB1 = *(const ulonglong2*)(wb + 512 * k4);
        ulonglong2 wA2 = *(const ulonglong2*)(wa + 512 * k4 + 256);
        ulonglong2 wB2 = *(const ulonglong2*)(wb + 512 * k4 + 256);

        #pragma unroll
        for (int bb = 0; bb < 4; ++bb) {
            acc[0][bb] = ffma2(hv[bb].x, wA1.x, acc[0][bb]);
            acc[1][bb] = ffma2(hv[bb].x, wA1.y, acc[1][bb]);
            acc[2][bb] = ffma2(hv[bb].x, wB1.x, acc[2][bb]);
            acc[3][bb] = ffma2(hv[bb].x, wB1.y, acc[3][bb]);
            acc[0][bb] = ffma2(hv[bb].y, wA2.x, acc[0][bb]);
            acc[1][bb] = ffma2(hv[bb].y, wA2.y, acc[1][bb]);
            acc[2][bb] = ffma2(hv[bb].y, wB2.x, acc[2][bb]);
            acc[3][bb] = ffma2(hv[bb].y, wB2.y, acc[3][bb]);
        }
    }
}

__global__ __launch_bounds__(NTHREADS)
void lstm2_fused_kernel(const float* __restrict__ x,
                        const float* __restrict__ w_ih0, const float* __restrict__ w_hh0,
                        const float* __restrict__ b_ih0, const float* __restrict__ b_hh0,
                        const float* __restrict__ w_ih1, const float* __restrict__ w_hh1,
                        const float* __restrict__ b_ih1, const float* __restrict__ b_hh1,
                        const float* __restrict__ w_fc,  const float* __restrict__ b_fc,
                        float* __restrict__ out)
{
    extern __shared__ float smem[];
    float* W0A  = smem + OFF_W0A;
    float* W0B  = smem + OFF_W0B;
    float* WI1A = smem + OFF_WI1A;
    float* WI1B = smem + OFF_WI1B;
    float* WH1A = smem + OFF_WH1A;
    float* WH1B = smem + OFF_WH1B;
    float* h0s  = smem + OFF_H0;
    float* h1s  = smem + OFF_H1;
    float* xbuf = smem + OFF_XB;

    const int tid   = threadIdx.x;
    const int bbase = blockIdx.x * BB;

    // ---- weights -> smem (gate-adjacent split layout) ----
    // idx enumerates (k2, m, g) float2 elements: 32*64*4 = 8192 per matrix
    for (int idx = tid; idx < 8192; idx += NTHREADS) {
        int k2 = idx >> 8;
        int m  = (idx >> 2) & 63;
        int g  = idx & 3;
        int srcoff = (g * 64 + m) * 64 + 2 * k2;
        int dsthalf = (g >> 1);            // 0 -> A, 1 -> B
        int dstoff = (k2 * 64 + m) * 4 + (g & 1) * 2;
        float2 v0 = *(const float2*)(w_hh0 + srcoff);
        float2 v1 = *(const float2*)(w_ih1 + srcoff);
        float2 v2 = *(const float2*)(w_hh1 + srcoff);
        *(float2*)((dsthalf ? W0B  : W0A)  + dstoff) = v0;
        *(float2*)((dsthalf ? WI1B : WI1A) + dstoff) = v1;
        *(float2*)((dsthalf ? WH1B : WH1A) + dstoff) = v2;
    }
    for (int idx = tid; idx < BB * 64; idx += NTHREADS) { h0s[idx] = 0.0f; h1s[idx] = 0.0f; }
    if (tid < BB) xbuf[tid] = x[(bbase + tid) * TSEQ + 0];

    // thread = (bg, m): hidden unit m, batch elems bg*4 .. bg*4+3, ALL 4 gates of that unit
    const int m  = tid & 63;
    const int bg = tid >> 6;
    const int m4 = m * 4;

    float bias0[4], bias1[4], wi0[4];
    #pragma unroll
    for (int g = 0; g < 4; ++g) {
        int j = g * 64 + m;
        bias0[g] = b_ih0[j] + b_hh0[j];
        bias1[g] = b_ih1[j] + b_hh1[j];
        wi0[g]   = w_ih0[j];
    }

    float c0[4] = {0.f, 0.f, 0.f, 0.f};
    float c1[4] = {0.f, 0.f, 0.f, 0.f};

    const float* hrow0 = h0s + bg * 256;   // 4 rows of 64
    const float* hrow1 = h1s + bg * 256;
    float* hw0 = h0s + bg * 256 + m;       // write slots (stride 64 per bb)
    float* hw1 = h1s + bg * 256 + m;
    const float* xrd = xbuf + bg * 4;

    __syncthreads();

    for (int t = 0; t < TSEQ; ++t) {
        ull acc[4][4];

        // ======== phase 1: layer-0 gates + in-register update ========
        #pragma unroll
        for (int g = 0; g < 4; ++g)
            #pragma unroll
            for (int bb = 0; bb < 4; ++bb) acc[g][bb] = 0ULL;
        gemm_unit(acc, W0A, W0B, hrow0, m4);

        #pragma unroll
        for (int bb = 0; bb < 4; ++bb) {
            float xv = xrd[bb];
            float s[4];
            #pragma unroll
            for (int g = 0; g < 4; ++g) {
                float lo, hi;
                unpack2(acc[g][bb], lo, hi);
                s[g] = fmaf(xv, wi0[g], bias0[g]) + (lo + hi);
            }
            float iv = sigm_(s[0]);
            float fv = sigm_(s[1]);
            float gv = tanh_(s[2]);
            float ov = sigm_(s[3]);
            c0[bb] = fmaf(fv, c0[bb], iv * gv);
            hw0[bb * 64] = ov * tanh_(c0[bb]);
        }
        __syncthreads();

        // ======== phase 2: layer-1 gates + in-register update ========
        #pragma unroll
        for (int g = 0; g < 4; ++g)
            #pragma unroll
            for (int bb = 0; bb < 4; ++bb) acc[g][bb] = 0ULL;
        gemm_unit(acc, WI1A, WI1B, hrow0, m4);
        gemm_unit(acc, WH1A, WH1B, hrow1, m4);

        #pragma unroll
        for (int bb = 0; bb < 4; ++bb) {
            float s[4];
            #pragma unroll
            for (int g = 0; g < 4; ++g) {
                float lo, hi;
                unpack2(acc[g][bb], lo, hi);
                s[g] = bias1[g] + (lo + hi);
            }
            float iv = sigm_(s[0]);
            float fv = sigm_(s[1]);
            float gv = tanh_(s[2]);
            float ov = sigm_(s[3]);
            c1[bb] = fmaf(fv, c1[bb], iv * gv);
            hw1[bb * 64] = ov * tanh_(c1[bb]);
        }
        if (t + 1 < TSEQ && tid < BB) xbuf[tid] = x[(bbase + tid) * TSEQ + (t + 1)];
        __syncthreads();
    }

    // ---- final FC ----
    if (tid < BB * 3) {
        int bb  = tid / 3;
        int cls = tid - bb * 3;
        float s = b_fc[cls];
        #pragma unroll 8
        for (int mm = 0; mm < 64; ++mm)
            s = fmaf(h1s[bb * 64 + mm], w_fc[cls * 64 + mm], s);
        out[(bbase + bb) * 3 + cls] = s;
    }
}

extern "C" void kernel_launch(void* const* d_in, const int* in_sizes, int n_in,
                              void* d_out, int out_size)
{
    const float* x     = (const float*)d_in[0];
    const float* w_ih0 = (const float*)d_in[1];
    const float* w_hh0 = (const float*)d_in[2];
    const float* b_ih0 = (const float*)d_in[3];
    const float* b_hh0 = (const float*)d_in[4];
    const float* w_ih1 = (const float*)d_in[5];
    const float* w_hh1 = (const float*)d_in[6];
    const float* b_ih1 = (const float*)d_in[7];
    const float* b_hh1 = (const float*)d_in[8];
    const float* w_fc  = (const float*)d_in[9];
    const float* b_fc  = (const float*)d_in[10];
    float* out = (float*)d_out;

    cudaFuncSetAttribute(lstm2_fused_kernel,
                         cudaFuncAttributeMaxDynamicSharedMemorySize, SMEM_BYTES);

    lstm2_fused_kernel<<<NBLOCKS, NTHREADS, SMEM_BYTES>>>(
        x, w_ih0, w_hh0, b_ih0, b_hh0,
        w_ih1, w_hh1, b_ih1, b_hh1,
        w_fc, b_fc, out);
}